// round 1
// baseline (speedup 1.0000x reference)
#include <cuda_runtime.h>
#include <cuda_bf16.h>
#include <mma.h>

using namespace nvcuda;

#define BB 32
#define SS 2048
#define DD 1024
#define CH 16           // s-chunks for the stats pass
#define SC (SS/CH)      // 128 rows per chunk

// ---- device scratch (no allocations allowed in kernel_launch) ----
__device__ __nv_bfloat16 g_xb[(size_t)BB * SS * DD];     // bf16 copy of x (134 MB)
__device__ float g_psum[BB * CH * DD];                    // partial sums
__device__ float g_psq [BB * CH * DD];                    // partial sums of squares
__device__ float g_mean[BB * DD];
__device__ float g_var [BB * DD];
__device__ float g_keep[BB * DD];                         // 1.0 keep / 0.0 kill

// ------------------------------------------------------------------
// Kernel 1a: per-(b, s-chunk) column partial sums + fp32->bf16 convert
// grid = BB*CH blocks, 256 threads; thread t handles columns [4t, 4t+4)
// ------------------------------------------------------------------
__global__ void stats_convert_kernel(const float* __restrict__ x) {
    int b = blockIdx.x / CH;
    int c = blockIdx.x % CH;
    int d0 = threadIdx.x * 4;

    float s0 = 0.f, s1 = 0.f, s2 = 0.f, s3 = 0.f;
    float q0 = 0.f, q1 = 0.f, q2 = 0.f, q3 = 0.f;

    #pragma unroll 4
    for (int r = 0; r < SC; ++r) {
        size_t off = ((size_t)b * SS + (size_t)c * SC + r) * DD + d0;
        float4 v = *(const float4*)(x + off);
        s0 += v.x; s1 += v.y; s2 += v.z; s3 += v.w;
        q0 += v.x * v.x; q1 += v.y * v.y; q2 += v.z * v.z; q3 += v.w * v.w;
        __nv_bfloat162 lo = __floats2bfloat162_rn(v.x, v.y);
        __nv_bfloat162 hi = __floats2bfloat162_rn(v.z, v.w);
        uint2 pk;
        pk.x = *(const unsigned int*)&lo;
        pk.y = *(const unsigned int*)&hi;
        *(uint2*)(g_xb + off) = pk;
    }

    int p = (b * CH + c) * DD + d0;
    g_psum[p + 0] = s0; g_psum[p + 1] = s1; g_psum[p + 2] = s2; g_psum[p + 3] = s3;
    g_psq [p + 0] = q0; g_psq [p + 1] = q1; g_psq [p + 2] = q2; g_psq [p + 3] = q3;
}

// ------------------------------------------------------------------
// Kernel 1b: reduce partials -> mean/var, init keep=1  (deterministic)
// ------------------------------------------------------------------
__global__ void finalize_stats_kernel() {
    int i = blockIdx.x * blockDim.x + threadIdx.x;   // 0 .. BB*DD
    int b = i / DD;
    int d = i % DD;
    float s = 0.f, q = 0.f;
    #pragma unroll
    for (int c = 0; c < CH; ++c) {
        s += g_psum[(b * CH + c) * DD + d];
        q += g_psq [(b * CH + c) * DD + d];
    }
    float mean = s * (1.0f / SS);
    float var  = (q - (float)SS * mean * mean) * (1.0f / (SS - 1));
    g_mean[i] = mean;
    g_var [i] = var;
    g_keep[i] = 1.0f;
}

// ------------------------------------------------------------------
// Kernel 2: per-batch Gram (bf16 wmma, fp32 accum) over 64x64 tiles of
// the upper triangle; epilogue does the corr-threshold kill test.
// grid = (16, 16, BB), 256 threads (8 warps, 2x4 warp grid of 32x16 tiles)
// ------------------------------------------------------------------
__global__ void gram_kernel() {
    int bi = blockIdx.x;
    int bj = blockIdx.y;
    int b  = blockIdx.z;
    if (bi > bj) return;   // upper triangle only (uniform per block)

    __shared__ __nv_bfloat16 As[32][72];   // [k][i], +8 pad
    __shared__ __nv_bfloat16 Bs[32][72];   // [k][j]
    __shared__ float Cs[64][68];

    int t    = threadIdx.x;
    int row  = t >> 3;          // 0..31 (k within chunk)
    int q    = (t & 7) * 8;     // 8 bf16 per thread per tile
    int wid  = t >> 5;
    int wm   = wid >> 2;        // 0..1 -> 32 rows
    int wn   = wid & 3;         // 0..3 -> 16 cols

    wmma::fragment<wmma::accumulator, 16, 16, 16, float> acc0, acc1;
    wmma::fill_fragment(acc0, 0.0f);
    wmma::fill_fragment(acc1, 0.0f);

    const __nv_bfloat16* xb = g_xb + (size_t)b * SS * DD;

    for (int kc = 0; kc < SS / 32; ++kc) {
        int s = kc * 32 + row;
        const __nv_bfloat16* src = xb + (size_t)s * DD;
        *(uint4*)&As[row][q] = *(const uint4*)(src + bi * 64 + q);
        *(uint4*)&Bs[row][q] = *(const uint4*)(src + bj * 64 + q);
        __syncthreads();

        #pragma unroll
        for (int k2 = 0; k2 < 32; k2 += 16) {
            wmma::fragment<wmma::matrix_a, 16, 16, 16, __nv_bfloat16, wmma::col_major> a0, a1;
            wmma::fragment<wmma::matrix_b, 16, 16, 16, __nv_bfloat16, wmma::row_major> bf;
            wmma::load_matrix_sync(a0, &As[k2][wm * 32],      72);
            wmma::load_matrix_sync(a1, &As[k2][wm * 32 + 16], 72);
            wmma::load_matrix_sync(bf, &Bs[k2][wn * 16],      72);
            wmma::mma_sync(acc0, a0, bf, acc0);
            wmma::mma_sync(acc1, a1, bf, acc1);
        }
        __syncthreads();
    }

    wmma::store_matrix_sync(&Cs[wm * 32     ][wn * 16], acc0, 68, wmma::mem_row_major);
    wmma::store_matrix_sync(&Cs[wm * 32 + 16][wn * 16], acc1, 68, wmma::mem_row_major);
    __syncthreads();

    const float invS1 = 1.0f / (SS - 1);
    for (int idx = t; idx < 64 * 64; idx += 256) {
        int ti = idx >> 6;
        int tj = idx & 63;
        int gi = bi * 64 + ti;
        int gj = bj * 64 + tj;
        if (gi >= gj) continue;                  // strict upper triangle, no diagonal
        float g   = Cs[ti][tj];
        float mi  = g_mean[b * DD + gi];
        float mj  = g_mean[b * DD + gj];
        float vi  = g_var [b * DD + gi];
        float vj  = g_var [b * DD + gj];
        float cov = (g - (float)SS * mi * mj) * invS1;
        if (cov * cov > 0.25f * vi * vj) {       // |corr| > 0.5
            g_keep[b * DD + gi] = 0.0f;          // symmetric: kill both columns
            g_keep[b * DD + gj] = 0.0f;
        }
    }
}

// ------------------------------------------------------------------
// Kernel 3: out = x * keep[b,d]   (float4-vectorized)
// ------------------------------------------------------------------
__global__ void apply_kernel(const float* __restrict__ x, float* __restrict__ out) {
    size_t idx = (size_t)blockIdx.x * blockDim.x + threadIdx.x;  // over n/4
    size_t e = idx * 4;
    int d = (int)(e & (DD - 1));
    int b = (int)(e / ((size_t)SS * DD));
    float4 v = ((const float4*)x)[idx];
    float4 k = *(const float4*)(g_keep + b * DD + d);
    v.x *= k.x; v.y *= k.y; v.z *= k.z; v.w *= k.w;
    ((float4*)out)[idx] = v;
}

// ------------------------------------------------------------------
extern "C" void kernel_launch(void* const* d_in, const int* in_sizes, int n_in,
                              void* d_out, int out_size) {
    const float* x = (const float*)d_in[0];
    float* out = (float*)d_out;

    stats_convert_kernel<<<BB * CH, 256>>>(x);
    finalize_stats_kernel<<<(BB * DD) / 256, 256>>>();
    gram_kernel<<<dim3(16, 16, BB), 256>>>();
    apply_kernel<<<(size_t)(BB * SS * DD / 4) / 256, 256>>>(x, out);
}

// round 9
// speedup vs baseline: 1.4884x; 1.4884x over previous
#include <cuda_runtime.h>
#include <cuda_bf16.h>
#include <mma.h>
#include <cstdint>

using namespace nvcuda;

#define BB 32
#define SS 2048
#define DD 1024
#define CH 16
#define SC (SS/CH)

// ---------------- device scratch (no allocs allowed) ----------------
__device__ __nv_bfloat16 g_xb[(size_t)BB * SS * DD];   // bf16 x, row-major [b][s][d]
__device__ float g_psum[BB * CH * DD];
__device__ float g_psq [BB * CH * DD];
__device__ float g_mean[BB * DD];
__device__ float g_var [BB * DD];
__device__ float g_keep[BB * DD];

__device__ __forceinline__ uint32_t smem_u32(const void* p) {
    uint32_t a;
    asm("{ .reg .u64 t; cvta.to.shared.u64 t, %1; cvt.u32.u64 %0, t; }" : "=r"(a) : "l"(p));
    return a;
}
#define CP_ASYNC16(sm, gm) \
    asm volatile("cp.async.cg.shared.global [%0], [%1], 16;" :: "r"(sm), "l"(gm) : "memory")
#define CP_COMMIT()   asm volatile("cp.async.commit_group;" ::: "memory")
#define CP_WAIT(n)    asm volatile("cp.async.wait_group %0;" :: "n"(n) : "memory")

// =====================================================================
// Kernel 1: per-(b, s-chunk) column partial sums + fp32->bf16 convert
// =====================================================================
__global__ void __launch_bounds__(256) stats_convert_kernel(const float* __restrict__ x) {
    int b = blockIdx.x / CH;
    int c = blockIdx.x % CH;
    int d0 = threadIdx.x * 4;

    float s0 = 0.f, s1 = 0.f, s2 = 0.f, s3 = 0.f;
    float q0 = 0.f, q1 = 0.f, q2 = 0.f, q3 = 0.f;

    #pragma unroll 4
    for (int r = 0; r < SC; ++r) {
        size_t off = ((size_t)b * SS + (size_t)c * SC + r) * DD + d0;
        float4 v = *(const float4*)(x + off);
        s0 += v.x; s1 += v.y; s2 += v.z; s3 += v.w;
        q0 += v.x * v.x; q1 += v.y * v.y; q2 += v.z * v.z; q3 += v.w * v.w;
        __nv_bfloat162 lo = __floats2bfloat162_rn(v.x, v.y);
        __nv_bfloat162 hi = __floats2bfloat162_rn(v.z, v.w);
        uint2 pk;
        pk.x = *(const unsigned int*)&lo;
        pk.y = *(const unsigned int*)&hi;
        *(uint2*)(g_xb + off) = pk;
    }
    int p = (b * CH + c) * DD + d0;
    *(float4*)(g_psum + p) = make_float4(s0, s1, s2, s3);
    *(float4*)(g_psq  + p) = make_float4(q0, q1, q2, q3);
}

// =====================================================================
// Kernel 2: reduce partials -> mean/var, init keep=1
// =====================================================================
__global__ void finalize_stats_kernel() {
    int i = blockIdx.x * 256 + threadIdx.x;
    int b = i >> 10, d = i & 1023;
    float s = 0.f, q = 0.f;
    #pragma unroll
    for (int c = 0; c < CH; ++c) {
        s += g_psum[(b * CH + c) * DD + d];
        q += g_psq [(b * CH + c) * DD + d];
    }
    float mean = s * (1.0f / SS);
    float var  = (q - (float)SS * mean * mean) * (1.0f / (SS - 1));
    g_mean[i] = mean; g_var[i] = var; g_keep[i] = 1.0f;
}

// =====================================================================
// Kernel 3: HMMA Gram, 128x128 tiles, 4-stage cp.async pipeline
//   8 warps in 2x4 grid; warp tile = 64(i) x 32(j)
//   smem stage: A[32k][128i] + B[32k][128j], pitch 136 bf16 (272B)
// =====================================================================
#define KB      32                      // k per slab
#define NSLAB   (SS / KB)               // 64
#define PITCH   136                     // bf16 elems per smem row
#define TBYTES  (KB * PITCH * 2)        // 8704 per tile
#define STAGEB  (2 * TBYTES)            // 17408
#define STAGES  4
#define DYNSMEM (STAGES * STAGEB)       // 69632 (C tile 128*132*4=67584 aliases)

// 36 upper-triangle pairs of 128-wide tiles over D=1024 (8 tiles)
__constant__ int c_bi[36] = {0, 0,1, 0,1,2, 0,1,2,3, 0,1,2,3,4, 0,1,2,3,4,5,
                             0,1,2,3,4,5,6, 0,1,2,3,4,5,6,7};
__constant__ int c_bj[36] = {0, 1,1, 2,2,2, 3,3,3,3, 4,4,4,4,4, 5,5,5,5,5,5,
                             6,6,6,6,6,6,6, 7,7,7,7,7,7,7,7};

__global__ void __launch_bounds__(256, 2) gram_kernel() {
    extern __shared__ __align__(16) uint8_t dyn[];
    __shared__ float s_mi[128], s_vi[128], s_mj[128], s_vj[128];

    int t = threadIdx.x, wid = t >> 5;
    int wm = wid >> 2;              // 0..1 -> 64-row half
    int wn = wid & 3;               // 0..3 -> 32-col quarter
    int b  = blockIdx.y;
    int i0 = c_bi[blockIdx.x] * 128;
    int j0 = c_bj[blockIdx.x] * 128;

    if (t < 128) {
        s_mi[t] = g_mean[b * DD + i0 + t];
        s_vi[t] = g_var [b * DD + i0 + t];
        s_mj[t] = g_mean[b * DD + j0 + t];
        s_vj[t] = g_var [b * DD + j0 + t];
    }

    const __nv_bfloat16* xb = g_xb + (size_t)b * SS * DD;
    uint32_t sbase = smem_u32(dyn);

    // per-thread chunk mapping: 4 chunks of 16B, c = i*256 + t
    //   tile = c>>9 (0=A/bi, 1=B/bj), r = (c>>4)&31, ch = c&15
    auto issue_slab = [&](int kc) {
        #pragma unroll
        for (int i = 0; i < 4; ++i) {
            int c    = i * 256 + t;
            int tile = c >> 9;
            int r    = (c >> 4) & 31;
            int ch   = c & 15;
            int dbase = (tile ? j0 : i0);
            const __nv_bfloat16* gp = xb + (size_t)(kc * KB + r) * DD + dbase + ch * 8;
            uint32_t sp = sbase + (uint32_t)((kc & (STAGES - 1)) * STAGEB
                                             + tile * TBYTES + r * (PITCH * 2) + ch * 16);
            CP_ASYNC16(sp, gp);
        }
        CP_COMMIT();
    };

    issue_slab(0); issue_slab(1); issue_slab(2);

    wmma::fragment<wmma::accumulator, 16, 16, 16, float> acc[4][2];
    #pragma unroll
    for (int x = 0; x < 4; ++x)
        #pragma unroll
        for (int y = 0; y < 2; ++y) wmma::fill_fragment(acc[x][y], 0.0f);

    for (int kc = 0; kc < NSLAB; ++kc) {
        CP_WAIT(2);
        __syncthreads();
        if (kc + 3 < NSLAB) issue_slab(kc + 3);

        const __nv_bfloat16* As = (const __nv_bfloat16*)(dyn + (kc & (STAGES - 1)) * STAGEB);
        const __nv_bfloat16* Bs = As + KB * PITCH;

        #pragma unroll
        for (int k2 = 0; k2 < KB; k2 += 16) {
            wmma::fragment<wmma::matrix_a, 16, 16, 16, __nv_bfloat16, wmma::col_major> a[4];
            wmma::fragment<wmma::matrix_b, 16, 16, 16, __nv_bfloat16, wmma::row_major> bf[2];
            #pragma unroll
            for (int x = 0; x < 4; ++x)
                wmma::load_matrix_sync(a[x], As + k2 * PITCH + wm * 64 + x * 16, PITCH);
            #pragma unroll
            for (int y = 0; y < 2; ++y)
                wmma::load_matrix_sync(bf[y], Bs + k2 * PITCH + wn * 32 + y * 16, PITCH);
            #pragma unroll
            for (int x = 0; x < 4; ++x)
                #pragma unroll
                for (int y = 0; y < 2; ++y)
                    wmma::mma_sync(acc[x][y], a[x], bf[y], acc[x][y]);
        }
    }

    // ---- epilogue: C into smem (aliases pipeline buffers), kill-test ----
    __syncthreads();
    float* Cs = (float*)dyn;   // 128 x 132
    #pragma unroll
    for (int x = 0; x < 4; ++x)
        #pragma unroll
        for (int y = 0; y < 2; ++y)
            wmma::store_matrix_sync(Cs + (wm * 64 + x * 16) * 132 + wn * 32 + y * 16,
                                    acc[x][y], 132, wmma::mem_row_major);
    __syncthreads();

    const float inv = 1.0f / (SS - 1);
    for (int idx = t; idx < 128 * 128; idx += 256) {
        int ti = idx >> 7, tj = idx & 127;
        int gi = i0 + ti, gj = j0 + tj;
        if (gi >= gj) continue;
        float cov = (Cs[ti * 132 + tj] - (float)SS * s_mi[ti] * s_mj[tj]) * inv;
        if (cov * cov > 0.25f * s_vi[ti] * s_vj[tj]) {
            g_keep[b * DD + gi] = 0.0f;
            g_keep[b * DD + gj] = 0.0f;
        }
    }
}

// =====================================================================
// Kernel 4: out = x * keep[b,d]
// =====================================================================
__global__ void __launch_bounds__(256) apply_kernel(const float* __restrict__ x,
                                                    float* __restrict__ out) {
    size_t idx = (size_t)blockIdx.x * blockDim.x + threadIdx.x;
    size_t e = idx * 4;
    int d = (int)(e & (DD - 1));
    int b = (int)(e / ((size_t)SS * DD));
    float4 v = ((const float4*)x)[idx];
    float4 k = *(const float4*)(g_keep + b * DD + d);
    v.x *= k.x; v.y *= k.y; v.z *= k.z; v.w *= k.w;
    ((float4*)out)[idx] = v;
}

// =====================================================================
extern "C" void kernel_launch(void* const* d_in, const int* in_sizes, int n_in,
                              void* d_out, int out_size) {
    const float* x = (const float*)d_in[0];
    float* out = (float*)d_out;

    cudaFuncSetAttribute(gram_kernel, cudaFuncAttributeMaxDynamicSharedMemorySize, DYNSMEM);

    stats_convert_kernel<<<BB * CH, 256>>>(x);
    finalize_stats_kernel<<<(BB * DD) / 256, 256>>>();
    gram_kernel<<<dim3(36, BB), 256, DYNSMEM>>>();
    apply_kernel<<<(size_t)(BB * SS * DD / 4) / 256, 256>>>(x, out);
}